// round 15
// baseline (speedup 1.0000x reference)
#include <cuda_runtime.h>
#include <cuda_fp16.h>
#include <cstdint>

// Problem constants
#define NN   4096
#define FIN  512
#define FOUT 256
// C (channels) = 4

// ---------------------------------------------------------------------------
// Scratch (allocation-free rule: __device__ globals)
// ---------------------------------------------------------------------------
__device__ __half g_xh[(size_t)NN * FIN];            // 4 MB  x (fp16 hi)
__device__ __half g_wT_hi[FOUT * FIN];               // 256 KB WsumT hi
__device__ __half g_wT_lo[FOUT * FIN];               // 256 KB WsumT lo
__device__ __half g_hT[FOUT * NN];                   // 2 MB  h^T (fp16)
__device__ float  g_part[4ull * NN * FOUT];          // 16 MB split-K partials

// ---------------------------------------------------------------------------
// PTX helpers (sm_80-era only; 'a'-gated features rejected by harness ptxas)
// ---------------------------------------------------------------------------
__device__ __forceinline__ uint32_t smem_u32(const void* p) {
    uint32_t a;
    asm("{ .reg .u64 t; cvta.to.shared.u64 t, %1; cvt.u32.u64 %0, t; }"
        : "=r"(a) : "l"(p));
    return a;
}
__device__ __forceinline__ void cp16(uint32_t sdst, const void* gsrc) {
    asm volatile("cp.async.cg.shared.global [%0], [%1], 16;"
                 :: "r"(sdst), "l"(gsrc) : "memory");
}
__device__ __forceinline__ void cp_commit() {
    asm volatile("cp.async.commit_group;" ::: "memory");
}
template <int N>
__device__ __forceinline__ void cp_wait() {
    asm volatile("cp.async.wait_group %0;" :: "n"(N) : "memory");
}
__device__ __forceinline__ void ldmx4(uint32_t& r0, uint32_t& r1,
                                      uint32_t& r2, uint32_t& r3, uint32_t a) {
    asm volatile("ldmatrix.sync.aligned.m8n8.x4.shared.b16 {%0,%1,%2,%3}, [%4];"
                 : "=r"(r0), "=r"(r1), "=r"(r2), "=r"(r3) : "r"(a));
}
__device__ __forceinline__ void hmma(float* d, const uint32_t* a,
                                     const uint32_t* b) {
    asm volatile(
        "mma.sync.aligned.m16n8k16.row.col.f32.f16.f16.f32 "
        "{%0,%1,%2,%3}, {%4,%5,%6,%7}, {%8,%9}, {%0,%1,%2,%3};"
        : "+f"(d[0]), "+f"(d[1]), "+f"(d[2]), "+f"(d[3])
        : "r"(a[0]), "r"(a[1]), "r"(a[2]), "r"(a[3]), "r"(b[0]), "r"(b[1]));
}

constexpr int SROW_B = 80;   // 64B data + 16B pad (K=32 tiles, gemm_h)

// ---------------------------------------------------------------------------
// K0a: x -> fp16 (hi only)
// ---------------------------------------------------------------------------
__global__ void x_split(const float* __restrict__ x) {
    size_t t = (size_t)blockIdx.x * blockDim.x + threadIdx.x;  // float4 idx
    float4 v = reinterpret_cast<const float4*>(x)[t];
    __half h[4] = {__float2half_rn(v.x), __float2half_rn(v.y),
                   __float2half_rn(v.z), __float2half_rn(v.w)};
    reinterpret_cast<uint2*>(g_xh)[t] = *reinterpret_cast<uint2*>(h);
}

// ---------------------------------------------------------------------------
// K0b: WsumT[j,k] = sum_c weight[k,j,c], fp16 hi/lo (transposed store)
// ---------------------------------------------------------------------------
__global__ void wsum_split(const float* __restrict__ weight) {
    int idx = blockIdx.x * blockDim.x + threadIdx.x;  // k*FOUT + j
    int k = idx >> 8, j = idx & 255;
    float4 w = reinterpret_cast<const float4*>(weight)[idx];
    float s = (w.x + w.y) + (w.z + w.w);
    __half hi = __float2half_rn(s);
    g_wT_hi[j * FIN + k] = hi;
    g_wT_lo[j * FIN + k] = __float2half_rn(s - __half2float(hi));
}

// ---------------------------------------------------------------------------
// K1: h^T[j,i] = sum_k WsumT[j,k]*x[i,k]  (2 products: Wh*xh + Wl*xh)
// CTA tile M=64(j) x N=128(i), KC=32, grid (4, 32) = 128, 3-stage cp.async.
// ---------------------------------------------------------------------------
constexpr int HF_KC    = 32;
constexpr int HF_NC    = FIN / HF_KC;                // 16
constexpr int HF_AMAT  = 64 * SROW_B;                // 5120 (per A matrix)
constexpr int HF_BMAT  = 128 * SROW_B;               // 10240
constexpr int HF_STAGE = 2 * HF_AMAT + HF_BMAT;      // 20480
constexpr int HF_SMEM  = 3 * HF_STAGE;               // 61440

__global__ __launch_bounds__(256, 1) void gemm_h_mma() {
    extern __shared__ char smem[];
    const uint32_t sb = smem_u32(smem);
    const int tid = threadIdx.x, wid = tid >> 5, lane = tid & 31;
    const int wm = wid >> 2;          // 0..1 : 32-row (j) block
    const int wn = wid & 3;           // 0..3 : 32-col (i) block
    const int m0 = blockIdx.x * 64;   // j base
    const int n0 = blockIdx.y * 128;  // i base

    float acc[2][4][4];
#pragma unroll
    for (int mi = 0; mi < 2; mi++)
#pragma unroll
        for (int ni = 0; ni < 4; ni++)
#pragma unroll
            for (int q = 0; q < 4; q++) acc[mi][ni][q] = 0.0f;

    auto load_chunk = [&](int c) {
        const uint32_t stage = sb + (uint32_t)(c % 3) * HF_STAGE;
        const int ke = c * HF_KC;
        {                                     // A: 64 rows x 64B, hi+lo
            int row = tid >> 2, c16 = tid & 3;
            uint32_t so = (uint32_t)(row * SROW_B + c16 * 16);
            size_t g = (size_t)(m0 + row) * FIN + ke + c16 * 8;
            cp16(stage + so,           g_wT_hi + g);
            cp16(stage + HF_AMAT + so, g_wT_lo + g);
        }
#pragma unroll
        for (int i = 0; i < 2; i++) {         // B: 128 rows x 64B (xh)
            int e = tid + i * 256;
            int row = e >> 2, c16 = e & 3;
            uint32_t so = (uint32_t)(row * SROW_B + c16 * 16);
            size_t g = (size_t)(n0 + row) * FIN + ke + c16 * 8;
            cp16(stage + 2 * HF_AMAT + so, g_xh + g);
        }
        cp_commit();
    };

    const uint32_t a_lane_off =
        (uint32_t)((wm * 32 + (lane & 15)) * SROW_B + ((lane >> 4) << 3) * 2);
    const uint32_t b_lane_off =
        (uint32_t)((wn * 32 + ((lane >> 4) << 3) + (lane & 7)) * SROW_B +
                   (((lane >> 3) & 1) << 3) * 2);

    load_chunk(0);
    load_chunk(1);
    load_chunk(2);

    for (int c = 0; c < HF_NC; c++) {
        {
            int rem = HF_NC - 1 - c;
            if (rem >= 2) cp_wait<2>(); else if (rem == 1) cp_wait<1>();
            else cp_wait<0>();
        }
        __syncthreads();
        const uint32_t stage = sb + (uint32_t)(c % 3) * HF_STAGE;
        const uint32_t aH = stage + a_lane_off;
        const uint32_t aL = stage + HF_AMAT + a_lane_off;
        const uint32_t bH = stage + 2 * HF_AMAT + b_lane_off;
#pragma unroll
        for (int ks = 0; ks < 2; ks++) {
            const uint32_t kb = (uint32_t)(ks * 32);
            uint32_t ah[2][4], al[2][4], bb[4][2];
#pragma unroll
            for (int mi = 0; mi < 2; mi++)
                ldmx4(ah[mi][0], ah[mi][1], ah[mi][2], ah[mi][3],
                      aH + kb + (uint32_t)(mi * 16 * SROW_B));
#pragma unroll
            for (int mi = 0; mi < 2; mi++)
                ldmx4(al[mi][0], al[mi][1], al[mi][2], al[mi][3],
                      aL + kb + (uint32_t)(mi * 16 * SROW_B));
#pragma unroll
            for (int nb = 0; nb < 2; nb++)
                ldmx4(bb[2 * nb][0], bb[2 * nb][1],
                      bb[2 * nb + 1][0], bb[2 * nb + 1][1],
                      bH + kb + (uint32_t)(nb * 16 * SROW_B));
#pragma unroll
            for (int mi = 0; mi < 2; mi++)
#pragma unroll
                for (int ni = 0; ni < 4; ni++) {
                    hmma(acc[mi][ni], ah[mi], bb[ni]);   // Wh * xh
                    hmma(acc[mi][ni], al[mi], bb[ni]);   // Wl * xh
                }
        }
        __syncthreads();
        if (c + 3 < HF_NC) load_chunk(c + 3);
    }

    // Epilogue: write h^T fp16 directly
    const int r_base = m0 + wm * 32 + (lane >> 2);       // j
    const int c_base = n0 + wn * 32 + (lane & 3) * 2;    // i
#pragma unroll
    for (int mi = 0; mi < 2; mi++)
#pragma unroll
        for (int h = 0; h < 2; h++) {
            const int j = r_base + mi * 16 + h * 8;
#pragma unroll
            for (int ni = 0; ni < 4; ni++) {
                __half2 v = __floats2half2_rn(acc[mi][ni][2 * h],
                                              acc[mi][ni][2 * h + 1]);
                *reinterpret_cast<__half2*>(
                    g_hT + (size_t)j * NN + c_base + ni * 8) = v;
            }
        }
}

// ---------------------------------------------------------------------------
// K2 (FUSED v4): part[sk][i,j] = sum_k (sum_c adjs[i,k,c]) * hT[j,k]
// adjs streamed via DEEP cp.async (fp32, L1-bypass, ~120KB in flight/SM —
// cp.async keeps HBM busy across __syncthreads; registers can't).
// Each lane LDS.128-reads the 8 fp32 cells of its m16k16 A-fragment from
// the fp32 ring (272B stride -> conflict-free), sums channels, packs fp16
// fragments in registers. No fp16 A tile, no STS, no A ldmatrix.
// CTA: M=128(i) x N=256(j), 512 thr, warp tile 16x128, splitK=4, grid 128.
// ---------------------------------------------------------------------------
constexpr int F_KC    = 16;                          // cells (k) per chunk
constexpr int F_NCH   = 1024 / F_KC;                 // 64 chunks
constexpr int FA_ROW  = 272;                         // 256B data + 16B pad
constexpr int FA_MAT  = 128 * FA_ROW;                // 34816 (fp32 A slot)
constexpr int FB_ROW  = 48;                          // 32B data + 16B pad
constexpr int FB_MAT  = 256 * FB_ROW;                // 12288 (fp16 B slot)
constexpr int F_SMEM  = 4 * (FA_MAT + FB_MAT);       // 188416

__global__ __launch_bounds__(512, 1) void mma_fused_k(
    const float* __restrict__ adjs) {
    extern __shared__ char smem[];
    const uint32_t sb  = smem_u32(smem);
    const uint32_t sbB = sb + 4 * FA_MAT;
    const int tid  = threadIdx.x;
    const int wid  = tid >> 5;
    const int lane = tid & 31;
    const int wm   = wid >> 1;          // 0..7 -> 16-row (i) block
    const int wn   = wid & 1;           // 0..1 -> 128-col (j) block
    const int m0   = blockIdx.x * 128;  // i base
    const int sk   = blockIdx.y;
    const int k0   = sk * 1024;         // cell units

    const float4* __restrict__ A4 = reinterpret_cast<const float4*>(adjs);

    float acc[16][4];
#pragma unroll
    for (int ni = 0; ni < 16; ni++)
#pragma unroll
        for (int q = 0; q < 4; q++) acc[ni][q] = 0.0f;

    // One commit per chunk: A fp32 (4 cp16/thread) + B fp16 (1 cp16/thread)
    auto cp_chunk = [&](int c) {
        if (c < F_NCH) {
            const uint32_t sa = sb + (uint32_t)(c & 3) * FA_MAT;
            const int kc0 = k0 + c * F_KC;
#pragma unroll
            for (int i = 0; i < 4; i++) {
                int e = tid + i * 512;
                int row = e >> 4, kc = e & 15;
                cp16(sa + (uint32_t)(row * FA_ROW + kc * 16),
                     A4 + (size_t)(m0 + row) * NN + kc0 + kc);
            }
            const uint32_t sbst = sbB + (uint32_t)(c & 3) * FB_MAT;
            int row = tid >> 1, c16 = tid & 1;
            cp16(sbst + (uint32_t)(row * FB_ROW + c16 * 16),
                 g_hT + (size_t)row * NN + kc0 + c16 * 8);
        }
        cp_commit();   // empty groups past the end keep wait counts aligned
    };

    // A fragment cell offsets within a slot (fp32 cells, 272B row stride)
    const int fr0 = wm * 16 + (lane >> 2);              // fragment row
    const int fkq = 2 * (lane & 3);                     // fragment kcell base
    const uint32_t a_off = (uint32_t)(fr0 * FA_ROW + fkq * 16);
    // B ldmatrix lane offset
    const uint32_t b_off =
        (uint32_t)((wn * 128 + ((lane >> 4) << 3) + (lane & 7)) * FB_ROW +
                   (((lane >> 3) & 1) << 4));

    cp_chunk(0); cp_chunk(1); cp_chunk(2);

    for (int c = 0; c < F_NCH; c++) {
        cp_wait<2>();        // chunk c landed (c+1, c+2 in flight)
        __syncthreads();     // all warps done with slot (c+3)&3 (chunk c-1)
        cp_chunk(c + 3);     // refill; HBM stays busy through the barrier

        // --- A fragment: 8 conflict-free LDS.128, sum channels, pack ---
        const char* ap = smem + (size_t)((c & 3) * FA_MAT) + a_off;
        float4 q0 = *reinterpret_cast<const float4*>(ap);
        float4 q1 = *reinterpret_cast<const float4*>(ap + 16);
        float4 q2 = *reinterpret_cast<const float4*>(ap + 8 * FA_ROW);
        float4 q3 = *reinterpret_cast<const float4*>(ap + 8 * FA_ROW + 16);
        float4 q4 = *reinterpret_cast<const float4*>(ap + 128);
        float4 q5 = *reinterpret_cast<const float4*>(ap + 144);
        float4 q6 = *reinterpret_cast<const float4*>(ap + 8 * FA_ROW + 128);
        float4 q7 = *reinterpret_cast<const float4*>(ap + 8 * FA_ROW + 144);
        uint32_t af[4];
        {
            __half2 p0 = __floats2half2_rn((q0.x + q0.y) + (q0.z + q0.w),
                                           (q1.x + q1.y) + (q1.z + q1.w));
            __half2 p1 = __floats2half2_rn((q2.x + q2.y) + (q2.z + q2.w),
                                           (q3.x + q3.y) + (q3.z + q3.w));
            __half2 p2 = __floats2half2_rn((q4.x + q4.y) + (q4.z + q4.w),
                                           (q5.x + q5.y) + (q5.z + q5.w));
            __half2 p3 = __floats2half2_rn((q6.x + q6.y) + (q6.z + q6.w),
                                           (q7.x + q7.y) + (q7.z + q7.w));
            af[0] = *reinterpret_cast<uint32_t*>(&p0);
            af[1] = *reinterpret_cast<uint32_t*>(&p1);
            af[2] = *reinterpret_cast<uint32_t*>(&p2);
            af[3] = *reinterpret_cast<uint32_t*>(&p3);
        }

        // --- B fragments + 16 HMMA ---
        const uint32_t bbase = sbB + (uint32_t)((c & 3) * FB_MAT) + b_off;
#pragma unroll
        for (int nb = 0; nb < 8; nb++) {
            uint32_t bb[2][2];
            ldmx4(bb[0][0], bb[0][1], bb[1][0], bb[1][1],
                  bbase + (uint32_t)(nb * 16 * FB_ROW));
            hmma(acc[2 * nb],     af, bb[0]);
            hmma(acc[2 * nb + 1], af, bb[1]);
        }
    }

    // Epilogue: fp32 partials
    const int r_base = m0 + wm * 16 + (lane >> 2);       // i
    const int c_base = wn * 128 + (lane & 3) * 2;        // j
#pragma unroll
    for (int h = 0; h < 2; h++) {
        const int row = r_base + h * 8;
        float* dst = g_part + ((size_t)sk * NN + row) * FOUT + c_base;
#pragma unroll
        for (int ni = 0; ni < 16; ni++)
            *reinterpret_cast<float2*>(dst + ni * 8) =
                make_float2(acc[ni][2 * h], acc[ni][2 * h + 1]);
    }
}

// ---------------------------------------------------------------------------
// Reduce: out[i,j,:] = sum_{sk<4} part[sk,i,j] + bias[i,j,:]
// ---------------------------------------------------------------------------
__global__ void reduce_kernel(const float* __restrict__ bias,
                              float* __restrict__ out) {
    const int t = blockIdx.x * blockDim.x + threadIdx.x;   // (i*256 + j)
    constexpr size_t P = (size_t)NN * FOUT;
    float s = (g_part[t] + g_part[t + P]) +
              (g_part[t + 2 * P] + g_part[t + 3 * P]);
    float4 b = reinterpret_cast<const float4*>(bias)[t];
    reinterpret_cast<float4*>(out)[t] =
        make_float4(s + b.x, s + b.y, s + b.z, s + b.w);
}

// ---------------------------------------------------------------------------
// launch
// ---------------------------------------------------------------------------
extern "C" void kernel_launch(void* const* d_in, const int* in_sizes, int n_in,
                              void* d_out, int out_size) {
    const float* x      = (const float*)d_in[0];
    const float* adjs   = (const float*)d_in[1];
    const float* weight = (const float*)d_in[2];
    const float* bias   = (const float*)d_in[3];
    float* out          = (float*)d_out;

    cudaFuncSetAttribute(gemm_h_mma,
                         cudaFuncAttributeMaxDynamicSharedMemorySize, HF_SMEM);
    cudaFuncSetAttribute(mma_fused_k,
                         cudaFuncAttributeMaxDynamicSharedMemorySize, F_SMEM);

    // Prep: x -> fp16, WsumT hi/lo
    x_split<<<(NN * FIN / 4) / 256, 256>>>(x);
    wsum_split<<<(FIN * FOUT) / 256, 256>>>(weight);
    // h^T = WsumT @ x^T  (HMMA, 2 products)
    gemm_h_mma<<<dim3(FOUT / 64, NN / 128), 256, HF_SMEM>>>();
    // Main fused GEMM: deep cp.async fp32 stream + in-register channel sum
    mma_fused_k<<<dim3(NN / 128, 4), 512, F_SMEM>>>(adjs);
    // Combine partials + bias
    reduce_kernel<<<(NN * FOUT) / 256, 256>>>(bias, out);
}